// round 5
// baseline (speedup 1.0000x reference)
#include <cuda_runtime.h>
#include <math.h>
#include <stdint.h>

#define IN_DIM 128
#define EMB    128
#define HID    64
#define NEG    0.2f
#define MAXN   10240   // padded to tile multiple

typedef unsigned long long ULL;

// ---------------- scratch (static device globals; no allocation) ------------
__device__ float g_z[MAXN * HID];
__device__ float g_S[MAXN * HID];
__device__ float g_embed[MAXN * HID];   // zero-padded to MAXN rows
__device__ float g_asrc[MAXN];
__device__ float g_adst[MAXN];
__device__ int   g_menc[MAXN];
__device__ float g_den[MAXN];
__device__ int   g_is64;

// ---------------- small helpers ---------------------------------------------
__device__ __forceinline__ int fenc(float f) {
    int b = __float_as_int(f);
    return b >= 0 ? b : (b ^ 0x7fffffff);
}
__device__ __forceinline__ float fdec(int e) {
    return __int_as_float(e >= 0 ? e : (e ^ 0x7fffffff));
}
__device__ __forceinline__ float sigm(float v) {
    return __fdividef(1.0f, 1.0f + __expf(-v));
}
__device__ __forceinline__ void edge_pair(const void* ei, int E, int N, int i,
                                          int& s, int& d)
{
    if (i >= E) { s = d = i - E; return; }
    if (g_is64) {
        const long long* p = (const long long*)ei;
        s = (int)p[i]; d = (int)p[E + i];
    } else {
        const int* p = (const int*)ei;
        s = p[i]; d = p[E + i];
    }
}

// packed f32x2 helpers
#define PACK_BCAST(out, f) \
    asm("mov.b64 %0, {%1, %1};" : "=l"(out) : "r"(__float_as_uint(f)))
#define FMA2(d, a, b) \
    asm("fma.rn.f32x2 %0, %1, %2, %0;" : "+l"(d) : "l"(a), "l"(b))
__device__ __forceinline__ float2 unpk(ULL v) {
    float2 r;
    asm("mov.b64 {%0, %1}, %2;" : "=f"(r.x), "=f"(r.y) : "l"(v));
    return r;
}

// ---------------- init (+ fused dtype detect) --------------------------------
__global__ void init_scratch(const void* ei, int N) {
    int i = blockIdx.x * blockDim.x + threadIdx.x;
    if (i == 0) {
        // detect edge_index dtype: genuine int64 has all first 32 values in [0,N)
        const long long* p = (const long long*)ei;
        int ok = 1;
        #pragma unroll
        for (int t = 0; t < 32; t++) {
            long long v = p[t];
            if (v < 0 || v >= (long long)N) ok = 0;
        }
        g_is64 = ok;
    }
    if (i < N * HID) g_S[i] = 0.0f;
    if (i < N) {
        g_den[i]  = 0.0f;
        g_menc[i] = (int)0x80000000;
    }
}

// ---------------- fused node forward -----------------------------------------
__global__ __launch_bounds__(256) void node_fwd(
    const float* __restrict__ x, const float* __restrict__ W1,
    const float* __restrict__ b1, const float* __restrict__ W2,
    const float* __restrict__ att_s, const float* __restrict__ att_d, int N)
{
    __shared__ float xs[32][IN_DIM];
    __shared__ float hs[32][EMB];
    __shared__ float zs[32][HID];
    const int tid = threadIdx.x;
    const int r0  = blockIdx.x * 32;

    for (int i = tid; i < 32 * IN_DIM; i += 256) {
        int r = i / IN_DIM, c = i % IN_DIM;
        xs[r][c] = (r0 + r < N) ? x[(size_t)(r0 + r) * IN_DIM + c] : 0.0f;
    }
    __syncthreads();

    {
        int col = tid & 127;
        int rg  = tid >> 7;
        float acc[16];
        #pragma unroll
        for (int j = 0; j < 16; j++) acc[j] = 0.0f;
        for (int k = 0; k < IN_DIM; k++) {
            float w = W1[k * EMB + col];
            #pragma unroll
            for (int j = 0; j < 16; j++) acc[j] += xs[rg + 2 * j][k] * w;
        }
        float bb = b1[col];
        #pragma unroll
        for (int j = 0; j < 16; j++)
            hs[rg + 2 * j][col] = fmaxf(acc[j] + bb, 0.0f);
    }
    __syncthreads();

    {
        int col = tid & 63;
        int rg  = tid >> 6;
        float acc[8];
        #pragma unroll
        for (int j = 0; j < 8; j++) acc[j] = 0.0f;
        for (int k = 0; k < EMB; k++) {
            float w = W2[k * HID + col];
            #pragma unroll
            for (int j = 0; j < 8; j++) acc[j] += hs[rg + 4 * j][k] * w;
        }
        #pragma unroll
        for (int j = 0; j < 8; j++) {
            int r = rg + 4 * j;
            zs[r][col] = acc[j];
            if (r0 + r < N) g_z[(size_t)(r0 + r) * HID + col] = acc[j];
        }
    }
    __syncthreads();

    if (tid < 32) {
        int r = tid;
        if (r0 + r < N) {
            float s1 = 0.0f, s2 = 0.0f;
            #pragma unroll
            for (int k = 0; k < HID; k++) {
                float zv = zs[r][k];
                s1 += zv * att_s[k];
                s2 += zv * att_d[k];
            }
            g_asrc[r0 + r] = s1;
            g_adst[r0 + r] = s2;
        }
    }
}

// ---------------- edge pass 1: segment max ------------------------------------
__global__ void edge_max(const void* __restrict__ ei, int E, int N) {
    int i = blockIdx.x * blockDim.x + threadIdx.x;
    int ET = E + N;
    if (i >= ET) return;
    int s, d;
    edge_pair(ei, E, N, i, s, d);
    float e = g_asrc[s] + g_adst[d];
    e = e > 0.0f ? e : NEG * e;
    atomicMax(&g_menc[d], fenc(e));
}

// ---------------- edge pass 2: scatter ----------------------------------------
__global__ __launch_bounds__(256) void edge_scatter(
    const void* __restrict__ ei, int E, int N)
{
    int warp = (blockIdx.x * blockDim.x + threadIdx.x) >> 5;
    int lane = threadIdx.x & 31;
    int ET = E + N;
    if (warp >= ET) return;
    int s, d;
    edge_pair(ei, E, N, warp, s, d);
    float e = g_asrc[s] + g_adst[d];
    e = e > 0.0f ? e : NEG * e;
    float ex = __expf(e - fdec(g_menc[d]));
    if (lane == 0) atomicAdd(&g_den[d], ex);
    const float* zr = g_z + (size_t)s * HID;
    float*       Sr = g_S + (size_t)d * HID;
    atomicAdd(Sr + lane,      ex * zr[lane]);
    atomicAdd(Sr + 32 + lane, ex * zr[32 + lane]);
}

// ---------------- normalize (+ zero-pad tail to MAXN) --------------------------
__global__ void normalize_embed(const float* __restrict__ gat_b, int N)
{
    int i = blockIdx.x * blockDim.x + threadIdx.x;
    if (i >= MAXN * HID) return;
    if (i < N * HID) {
        int n = i >> 6, f = i & 63;
        g_embed[i] = g_S[i] / g_den[n] + gat_b[f];
    } else {
        g_embed[i] = 0.0f;
    }
}

// ---------------- copy embed into output tail ---------------------------------
__global__ void copy_embed(float* __restrict__ out_embed, int N)
{
    int i = blockIdx.x * blockDim.x + threadIdx.x;
    if (i < N * HID) out_embed[i] = g_embed[i];
}

// ---------------- sim = sigmoid(Z Z^T): f32x2 FMA + symmetric tiles ------------
// 128x128 tile, K=64 single-shot. Upper-triangular blocks only; each block
// writes its tile and (off-diagonal) its transpose. All stores are full
// 32B-sector (straight rows = 128B-coalesced across the warp; transposed rows
// = one aligned 32B chunk per row per thread).
#define LDP 132                      // padded row length (floats) in smem
#define SIM_SMEM (2 * HID * LDP * 4) // 67584 bytes

__global__ __launch_bounds__(256, 2) void sim_f32x2(float* __restrict__ out, int N)
{
    const int bi = blockIdx.y;       // M tile
    const int bj = blockIdx.x;       // N tile
    if (bi > bj) return;             // symmetry: upper triangle only

    extern __shared__ float sm[];
    float* As = sm;                  // As[k*LDP + r] = Z[i0+r][k]
    float* Bs = sm + HID * LDP;      // Bs[k*LDP + c] = Z[j0+c][k]

    const int tid = threadIdx.x;
    const int i0 = bi * 128;
    const int j0 = bj * 128;

    // ---- cooperative load: 128 rows x 64 floats each side, transposed ----
    {
        const float4* Zi = (const float4*)(g_embed + (size_t)i0 * HID);
        const float4* Zj = (const float4*)(g_embed + (size_t)j0 * HID);
        #pragma unroll
        for (int it = 0; it < 8; it++) {
            int idx = tid + it * 256;        // 0..2047
            int row = idx >> 4;              // 0..127
            int q   = idx & 15;              // float4 index within row
            float4 va = Zi[row * 16 + q];
            float4 vb = Zj[row * 16 + q];
            int k = q * 4;
            As[(k + 0) * LDP + row] = va.x;
            As[(k + 1) * LDP + row] = va.y;
            As[(k + 2) * LDP + row] = va.z;
            As[(k + 3) * LDP + row] = va.w;
            Bs[(k + 0) * LDP + row] = vb.x;
            Bs[(k + 1) * LDP + row] = vb.y;
            Bs[(k + 2) * LDP + row] = vb.z;
            Bs[(k + 3) * LDP + row] = vb.w;
        }
    }
    __syncthreads();

    // ---- mainloop: 8x8 per thread, accumulators as packed f32x2 pairs ----
    const int tx = tid & 15;         // col group: cols tx*8 .. +7
    const int ty = tid >> 4;         // row group: rows ty*8 .. +7
    const int a_off = ty * 8;
    const int b_off = tx * 8;

    ULL acc[8][4];
    #pragma unroll
    for (int r = 0; r < 8; r++)
        #pragma unroll
        for (int c = 0; c < 4; c++) acc[r][c] = 0ULL;

    #pragma unroll 4
    for (int k = 0; k < HID; k++) {
        const float* ar = As + k * LDP + a_off;
        const float* br = Bs + k * LDP + b_off;
        float4 a0 = *(const float4*)ar;
        float4 a1 = *(const float4*)(ar + 4);
        ulonglong2 bq0 = *(const ulonglong2*)br;        // pairs (c0,c1),(c2,c3)
        ulonglong2 bq1 = *(const ulonglong2*)(br + 4);  // pairs (c4,c5),(c6,c7)
        ULL bp0 = bq0.x, bp1 = bq0.y, bp2 = bq1.x, bp3 = bq1.y;
        float av[8] = {a0.x, a0.y, a0.z, a0.w, a1.x, a1.y, a1.z, a1.w};
        #pragma unroll
        for (int r = 0; r < 8; r++) {
            ULL ap;
            PACK_BCAST(ap, av[r]);
            FMA2(acc[r][0], ap, bp0);
            FMA2(acc[r][1], ap, bp1);
            FMA2(acc[r][2], ap, bp2);
            FMA2(acc[r][3], ap, bp3);
        }
    }

    // ---- epilogue: full 8x8 sigmoid in registers, sector-aligned dual write ----
    float v[8][8];
    #pragma unroll
    for (int r = 0; r < 8; r++)
        #pragma unroll
        for (int cp = 0; cp < 4; cp++) {
            float2 u = unpk(acc[r][cp]);
            v[r][cp * 2 + 0] = sigm(u.x);
            v[r][cp * 2 + 1] = sigm(u.y);
        }

    // straight tile: rows i0+a_off+r, contiguous 32B cols j0+b_off..+7
    #pragma unroll
    for (int r = 0; r < 8; r++) {
        int gi = i0 + a_off + r;
        if (gi >= N) continue;
        int gj = j0 + b_off;
        float* orow = out + (size_t)gi * N + gj;
        if (gj + 7 < N) {
            *(float4*)orow       = make_float4(v[r][0], v[r][1], v[r][2], v[r][3]);
            *(float4*)(orow + 4) = make_float4(v[r][4], v[r][5], v[r][6], v[r][7]);
        } else {
            #pragma unroll
            for (int c = 0; c < 8; c++)
                if (gj + c < N) orow[c] = v[r][c];
        }
    }

    // transposed tile: rows j0+b_off+c, contiguous 32B cols i0+a_off..+7
    if (bi != bj) {
        #pragma unroll
        for (int c = 0; c < 8; c++) {
            int gi = j0 + b_off + c;
            if (gi >= N) continue;
            int gj = i0 + a_off;
            float* orow = out + (size_t)gi * N + gj;
            if (gj + 7 < N) {
                *(float4*)orow       = make_float4(v[0][c], v[1][c], v[2][c], v[3][c]);
                *(float4*)(orow + 4) = make_float4(v[4][c], v[5][c], v[6][c], v[7][c]);
            } else {
                #pragma unroll
                for (int r = 0; r < 8; r++)
                    if (gj + r < N) orow[r] = v[r][c];
            }
        }
    }
}

// ---------------- launch --------------------------------------------------------
extern "C" void kernel_launch(void* const* d_in, const int* in_sizes, int n_in,
                              void* d_out, int out_size)
{
    const float* x    = (const float*)d_in[0];
    const void*  ei   = d_in[1];
    const float* W1   = (const float*)d_in[2];
    const float* b1   = (const float*)d_in[3];
    const float* W2   = (const float*)d_in[4];
    const float* atts = (const float*)d_in[5];
    const float* attd = (const float*)d_in[6];
    const float* gb   = (const float*)d_in[7];

    const int N = in_sizes[0] / IN_DIM;
    const int E = in_sizes[1] / 2;
    const int ET = E + N;

    float* out = (float*)d_out;

    static int smem_set = 0;
    if (!smem_set) {
        cudaFuncSetAttribute(sim_f32x2, cudaFuncAttributeMaxDynamicSharedMemorySize,
                             SIM_SMEM);
        smem_set = 1;
    }

    // launch order keeps sim_f32x2 as the 6th launch (ncu -s 5 -c 1 capture)
    init_scratch<<<(N * HID + 255) / 256, 256>>>(ei, N);              // 1
    node_fwd<<<(N + 31) / 32, 256>>>(x, W1, b1, W2, atts, attd, N);   // 2
    edge_max<<<(ET + 255) / 256, 256>>>(ei, E, N);                    // 3
    edge_scatter<<<(ET * 32 + 255) / 256, 256>>>(ei, E, N);           // 4
    normalize_embed<<<(MAXN * HID + 255) / 256, 256>>>(gb, N);        // 5

    const int nt = (N + 127) / 128;
    dim3 grid(nt, nt);
    sim_f32x2<<<grid, 256, SIM_SMEM>>>(out, N);                       // 6

    if ((size_t)out_size >= (size_t)N * N + (size_t)N * HID) {
        copy_embed<<<(N * HID + 255) / 256, 256>>>(out + (size_t)N * N, N);  // 7
    }
}

// round 6
// speedup vs baseline: 1.1024x; 1.1024x over previous
#include <cuda_runtime.h>
#include <math.h>
#include <stdint.h>

#define IN_DIM 128
#define EMB    128
#define HID    64
#define NEG    0.2f
#define MAXN   10240   // padded

typedef unsigned int uint32;

// ---------------- scratch (static device globals; no allocation) ------------
__device__ float g_z[MAXN * HID];
__device__ float g_S[MAXN * HID];
__device__ float g_asrc[MAXN];
__device__ float g_adst[MAXN];
__device__ int   g_menc[MAXN];
__device__ float g_den[MAXN];
__device__ int   g_is64;

// ---------------- small helpers ---------------------------------------------
__device__ __forceinline__ int fenc(float f) {
    int b = __float_as_int(f);
    return b >= 0 ? b : (b ^ 0x7fffffff);
}
__device__ __forceinline__ float fdec(int e) {
    return __int_as_float(e >= 0 ? e : (e ^ 0x7fffffff));
}
__device__ __forceinline__ float sigm(float v) {
    return __fdividef(1.0f, 1.0f + __expf(-v));
}
__device__ __forceinline__ void edge_pair(const void* ei, int E, int N, int i,
                                          int& s, int& d)
{
    if (i >= E) { s = d = i - E; return; }
    if (g_is64) {
        const long long* p = (const long long*)ei;
        s = (int)p[i]; d = (int)p[E + i];
    } else {
        const int* p = (const int*)ei;
        s = p[i]; d = p[E + i];
    }
}

// tf32 round (result bit pattern is a valid fp32 with low mantissa zeroed)
__device__ __forceinline__ uint32 to_tf32(float v) {
    uint32 r;
    asm("cvt.rna.tf32.f32 %0, %1;" : "=r"(r) : "f"(v));
    return r;
}

// m16n8k8 tf32 mma, D==C accumulate
#define MMA_TF32(cr, a, b0, b1)                                            \
    asm volatile(                                                          \
        "mma.sync.aligned.m16n8k8.row.col.f32.tf32.tf32.f32 "              \
        "{%0,%1,%2,%3}, {%4,%5,%6,%7}, {%8,%9}, {%0,%1,%2,%3};"            \
        : "+f"((cr)[0]), "+f"((cr)[1]), "+f"((cr)[2]), "+f"((cr)[3])       \
        : "r"((a)[0]), "r"((a)[1]), "r"((a)[2]), "r"((a)[3]),              \
          "r"(b0), "r"(b1))

// ---------------- launch 1: init + dtype detect + node forward ---------------
__global__ __launch_bounds__(256) void node_fwd_init(
    const float* __restrict__ x, const float* __restrict__ W1,
    const float* __restrict__ b1, const float* __restrict__ W2,
    const float* __restrict__ att_s, const float* __restrict__ att_d,
    const void* __restrict__ ei, int N)
{
    const int tid = threadIdx.x;
    const int gtid = blockIdx.x * 256 + tid;
    const int nthr = gridDim.x * 256;

    // scratch init (completes before edge kernels at launch boundary)
    for (int i = gtid; i < MAXN * HID; i += nthr) g_S[i] = 0.0f;
    for (int i = gtid; i < MAXN; i += nthr) {
        g_den[i]  = (i < N) ? 0.0f : 1.0f;   // pad rows: finite normalize
        g_menc[i] = (int)0x80000000;
    }
    if (gtid == 0) {
        const long long* p = (const long long*)ei;
        int ok = 1;
        #pragma unroll
        for (int t = 0; t < 32; t++) {
            long long v = p[t];
            if (v < 0 || v >= (long long)N) ok = 0;
        }
        g_is64 = ok;
    }

    // node forward
    __shared__ float xs[32][IN_DIM];
    __shared__ float hs[32][EMB];
    __shared__ float zs[32][HID];
    const int r0 = blockIdx.x * 32;

    for (int i = tid; i < 32 * IN_DIM; i += 256) {
        int r = i / IN_DIM, c = i % IN_DIM;
        xs[r][c] = (r0 + r < N) ? x[(size_t)(r0 + r) * IN_DIM + c] : 0.0f;
    }
    __syncthreads();

    {
        int col = tid & 127;
        int rg  = tid >> 7;
        float acc[16];
        #pragma unroll
        for (int j = 0; j < 16; j++) acc[j] = 0.0f;
        for (int k = 0; k < IN_DIM; k++) {
            float w = W1[k * EMB + col];
            #pragma unroll
            for (int j = 0; j < 16; j++) acc[j] += xs[rg + 2 * j][k] * w;
        }
        float bb = b1[col];
        #pragma unroll
        for (int j = 0; j < 16; j++)
            hs[rg + 2 * j][col] = fmaxf(acc[j] + bb, 0.0f);
    }
    __syncthreads();

    {
        int col = tid & 63;
        int rg  = tid >> 6;
        float acc[8];
        #pragma unroll
        for (int j = 0; j < 8; j++) acc[j] = 0.0f;
        for (int k = 0; k < EMB; k++) {
            float w = W2[k * HID + col];
            #pragma unroll
            for (int j = 0; j < 8; j++) acc[j] += hs[rg + 4 * j][k] * w;
        }
        #pragma unroll
        for (int j = 0; j < 8; j++) {
            int r = rg + 4 * j;
            zs[r][col] = acc[j];
            if (r0 + r < N) g_z[(size_t)(r0 + r) * HID + col] = acc[j];
        }
    }
    __syncthreads();

    if (tid < 32) {
        int r = tid;
        if (r0 + r < N) {
            float s1 = 0.0f, s2 = 0.0f;
            #pragma unroll
            for (int k = 0; k < HID; k++) {
                float zv = zs[r][k];
                s1 += zv * att_s[k];
                s2 += zv * att_d[k];
            }
            g_asrc[r0 + r] = s1;
            g_adst[r0 + r] = s2;
        }
    }
}

// ---------------- launch 2: segment max --------------------------------------
__global__ void edge_max(const void* __restrict__ ei, int E, int N) {
    int i = blockIdx.x * blockDim.x + threadIdx.x;
    int ET = E + N;
    if (i >= ET) return;
    int s, d;
    edge_pair(ei, E, N, i, s, d);
    float e = g_asrc[s] + g_adst[d];
    e = e > 0.0f ? e : NEG * e;
    atomicMax(&g_menc[d], fenc(e));
}

// ---------------- launch 3: scatter (8 threads/edge, red.v4) ------------------
__global__ __launch_bounds__(256) void edge_scatter(
    const void* __restrict__ ei, int E, int N)
{
    int gid  = blockIdx.x * blockDim.x + threadIdx.x;
    int eidx = gid >> 3;
    int sub  = gid & 7;
    int ET = E + N;
    if (eidx >= ET) return;
    int s, d;
    edge_pair(ei, E, N, eidx, s, d);
    float e = g_asrc[s] + g_adst[d];
    e = e > 0.0f ? e : NEG * e;
    float ex = __expf(e - fdec(g_menc[d]));
    if (sub == 0) atomicAdd(&g_den[d], ex);

    const float4* zr = (const float4*)(g_z + (size_t)s * HID);
    float4 z1 = zr[sub];
    float4 z2 = zr[sub + 8];
    float* p1 = g_S + (size_t)d * HID + sub * 4;
    float* p2 = p1 + 32;
    asm volatile("red.global.add.v4.f32 [%0], {%1,%2,%3,%4};"
                 :: "l"(p1), "f"(ex * z1.x), "f"(ex * z1.y),
                    "f"(ex * z1.z), "f"(ex * z1.w) : "memory");
    asm volatile("red.global.add.v4.f32 [%0], {%1,%2,%3,%4};"
                 :: "l"(p2), "f"(ex * z2.x), "f"(ex * z2.y),
                    "f"(ex * z2.z), "f"(ex * z2.w) : "memory");
}

// ---------------- launch 4: sim = sigmoid(Z Z^T) via tf32-split mma ----------
// 128x128 tile per block, 256 thr (8 warps, each 64x32), K in 2 chunks of 32.
// Normalize (S/den + b) fused into the tile loader; hi/lo tf32 split in regs.
#define LDA 36                                  // padded row (words): bank-bijective
#define SIM_SMEM (4 * 128 * LDA * 4)            // Ah,Al,Bh,Bl = 73728 B

__global__ __launch_bounds__(256, 2) void sim_mma(
    float* __restrict__ out, const float* __restrict__ gat_b, int N)
{
    const int bi = blockIdx.y, bj = blockIdx.x;
    if (bi > bj) return;

    extern __shared__ float sm[];
    float* Ah = sm;
    float* Al = sm + 128 * LDA;
    float* Bh = sm + 2 * 128 * LDA;
    float* Bl = sm + 3 * 128 * LDA;

    const int tid  = threadIdx.x;
    const int lane = tid & 31, wid = tid >> 5;
    const int g = lane >> 2, t = lane & 3;
    const int wrow = (wid & 1) * 64;
    const int wcol = (wid >> 1) * 32;
    const int i0 = bi * 128, j0 = bj * 128;

    float c[4][4][4];
    #pragma unroll
    for (int mt = 0; mt < 4; mt++)
        #pragma unroll
        for (int nt = 0; nt < 4; nt++)
            #pragma unroll
            for (int e = 0; e < 4; e++) c[mt][nt][e] = 0.0f;

    #pragma unroll
    for (int kc = 0; kc < 2; kc++) {
        const int k0 = kc * 32;
        if (kc) __syncthreads();   // previous chunk reads done before refill

        // ---- fill: load S, normalize, tf32 split, store hi/lo ----
        #pragma unroll
        for (int it = 0; it < 8; it++) {
            int idx  = tid + it * 256;       // 0..2047
            int side = idx >> 10;            // 0 = A rows, 1 = B rows
            int row  = (idx >> 3) & 127;
            int q    = idx & 7;              // float4 within 32-float chunk
            int grow = (side ? j0 : i0) + row;
            float4 sv = *(const float4*)(g_S + (size_t)grow * HID + k0 + q * 4);
            float  rd = __fdividef(1.0f, g_den[grow]);
            float4 bb = *(const float4*)(gat_b + k0 + q * 4);
            float v0 = sv.x * rd + bb.x;
            float v1 = sv.y * rd + bb.y;
            float v2 = sv.z * rd + bb.z;
            float v3 = sv.w * rd + bb.w;
            uint32 h0 = to_tf32(v0), h1 = to_tf32(v1);
            uint32 h2 = to_tf32(v2), h3 = to_tf32(v3);
            float* H = side ? Bh : Ah;
            float* L = side ? Bl : Al;
            int w = row * LDA + q * 4;
            *(float4*)(H + w) = make_float4(
                __uint_as_float(h0), __uint_as_float(h1),
                __uint_as_float(h2), __uint_as_float(h3));
            *(float4*)(L + w) = make_float4(
                v0 - __uint_as_float(h0), v1 - __uint_as_float(h1),
                v2 - __uint_as_float(h2), v3 - __uint_as_float(h3));
        }
        __syncthreads();

        // ---- mainloop: 4 k-steps of 8 ----
        #pragma unroll
        for (int ks = 0; ks < 4; ks++) {
            uint32 ah[4][4], al[4][4];
            #pragma unroll
            for (int mt = 0; mt < 4; mt++) {
                int ra = (wrow + mt * 16 + g) * LDA + ks * 8 + t;
                ah[mt][0] = __float_as_uint(Ah[ra]);
                ah[mt][1] = __float_as_uint(Ah[ra + 8 * LDA]);
                ah[mt][2] = __float_as_uint(Ah[ra + 4]);
                ah[mt][3] = __float_as_uint(Ah[ra + 8 * LDA + 4]);
                al[mt][0] = __float_as_uint(Al[ra]);
                al[mt][1] = __float_as_uint(Al[ra + 8 * LDA]);
                al[mt][2] = __float_as_uint(Al[ra + 4]);
                al[mt][3] = __float_as_uint(Al[ra + 8 * LDA + 4]);
            }
            #pragma unroll
            for (int nt = 0; nt < 4; nt++) {
                int rb = (wcol + nt * 8 + g) * LDA + ks * 8 + t;
                uint32 bh0 = __float_as_uint(Bh[rb]);
                uint32 bh1 = __float_as_uint(Bh[rb + 4]);
                uint32 bl0 = __float_as_uint(Bl[rb]);
                uint32 bl1 = __float_as_uint(Bl[rb + 4]);
                #pragma unroll
                for (int mt = 0; mt < 4; mt++) {
                    MMA_TF32(c[mt][nt], ah[mt], bh0, bh1);
                    MMA_TF32(c[mt][nt], ah[mt], bl0, bl1);
                    MMA_TF32(c[mt][nt], al[mt], bh0, bh1);
                }
            }
        }
    }
    __syncthreads();

    // ---- epilogue: sigmoid -> stage (reuses smem) -> coalesced dual write ----
    float* stage = sm;   // 128 x 132 floats = 67584 B < SIM_SMEM
    #pragma unroll
    for (int mt = 0; mt < 4; mt++)
        #pragma unroll
        for (int nt = 0; nt < 4; nt++) {
            int rs = wrow + mt * 16 + g;
            int cs = wcol + nt * 8 + 2 * t;
            stage[rs * 132 + cs]           = sigm(c[mt][nt][0]);
            stage[rs * 132 + cs + 1]       = sigm(c[mt][nt][1]);
            stage[(rs + 8) * 132 + cs]     = sigm(c[mt][nt][2]);
            stage[(rs + 8) * 132 + cs + 1] = sigm(c[mt][nt][3]);
        }
    __syncthreads();

    // straight tile
    for (int it = tid; it < 128 * 32; it += 256) {
        int row = it >> 5, cq = it & 31;
        int gi = i0 + row, gj = j0 + cq * 4;
        if (gi >= N || gj >= N) continue;
        const float* sp = stage + row * 132 + cq * 4;
        if (gj + 3 < N) {
            *(float4*)(out + (size_t)gi * N + gj) =
                make_float4(sp[0], sp[1], sp[2], sp[3]);
        } else {
            #pragma unroll
            for (int e = 0; e < 4; e++)
                if (gj + e < N) out[(size_t)gi * N + gj + e] = sp[e];
        }
    }
    // transposed tile
    if (bi != bj) {
        for (int it = tid; it < 128 * 32; it += 256) {
            int crow = it >> 5, rq = it & 31;
            int gi = j0 + crow, gj = i0 + rq * 4;
            if (gi >= N || gj >= N) continue;
            float4 v = make_float4(stage[(rq * 4 + 0) * 132 + crow],
                                   stage[(rq * 4 + 1) * 132 + crow],
                                   stage[(rq * 4 + 2) * 132 + crow],
                                   stage[(rq * 4 + 3) * 132 + crow]);
            if (gj + 3 < N) {
                *(float4*)(out + (size_t)gi * N + gj) = v;
            } else {
                const float vv[4] = {v.x, v.y, v.z, v.w};
                #pragma unroll
                for (int e = 0; e < 4; e++)
                    if (gj + e < N) out[(size_t)gi * N + gj + e] = vv[e];
            }
        }
    }
}

// ---------------- launch 5: embed output tail ---------------------------------
__global__ void copy_embed(float* __restrict__ out_embed,
                           const float* __restrict__ gat_b, int N)
{
    int i = blockIdx.x * blockDim.x + threadIdx.x;
    if (i >= N * HID) return;
    int n = i >> 6, f = i & 63;
    out_embed[i] = g_S[i] / g_den[n] + gat_b[f];
}

// ---------------- launch --------------------------------------------------------
extern "C" void kernel_launch(void* const* d_in, const int* in_sizes, int n_in,
                              void* d_out, int out_size)
{
    const float* x    = (const float*)d_in[0];
    const void*  ei   = d_in[1];
    const float* W1   = (const float*)d_in[2];
    const float* b1   = (const float*)d_in[3];
    const float* W2   = (const float*)d_in[4];
    const float* atts = (const float*)d_in[5];
    const float* attd = (const float*)d_in[6];
    const float* gb   = (const float*)d_in[7];

    const int N = in_sizes[0] / IN_DIM;
    const int E = in_sizes[1] / 2;
    const int ET = E + N;

    float* out = (float*)d_out;

    static int smem_set = 0;
    if (!smem_set) {
        cudaFuncSetAttribute(sim_mma, cudaFuncAttributeMaxDynamicSharedMemorySize,
                             SIM_SMEM);
        smem_set = 1;
    }

    node_fwd_init<<<(N + 31) / 32, 256>>>(x, W1, b1, W2, atts, attd, ei, N); // 1
    edge_max<<<(ET + 255) / 256, 256>>>(ei, E, N);                           // 2
    edge_scatter<<<(ET * 8 + 255) / 256, 256>>>(ei, E, N);                   // 3

    const int nt = (N + 127) / 128;
    dim3 grid(nt, nt);
    sim_mma<<<grid, 256, SIM_SMEM>>>(out, gb, N);                            // 4

    if ((size_t)out_size >= (size_t)N * N + (size_t)N * HID) {
        copy_embed<<<(N * HID + 255) / 256, 256>>>(out + (size_t)N * N, gb, N); // 5
    }
}

// round 7
// speedup vs baseline: 1.2110x; 1.0984x over previous
#include <cuda_runtime.h>
#include <cuda_bf16.h>
#include <math.h>
#include <stdint.h>

#define IN_DIM 128
#define EMB    128
#define HID    64
#define NEG    0.2f
#define MAXN   10240   // padded

typedef unsigned int uint32;

// ---------------- scratch (static device globals; no allocation) ------------
__device__ float g_z[MAXN * HID];
__device__ float g_S[MAXN * HID];
__device__ float g_asrc[MAXN];
__device__ float g_adst[MAXN];
__device__ int   g_menc[MAXN];
__device__ float g_den[MAXN];
__device__ int   g_is64;

// ---------------- small helpers ---------------------------------------------
__device__ __forceinline__ int fenc(float f) {
    int b = __float_as_int(f);
    return b >= 0 ? b : (b ^ 0x7fffffff);
}
__device__ __forceinline__ float fdec(int e) {
    return __int_as_float(e >= 0 ? e : (e ^ 0x7fffffff));
}
__device__ __forceinline__ float sigm(float v) {
    return __fdividef(1.0f, 1.0f + __expf(-v));
}
__device__ __forceinline__ void edge_pair(const void* ei, int E, int N, int i,
                                          int& s, int& d)
{
    if (i >= E) { s = d = i - E; return; }
    if (g_is64) {
        const long long* p = (const long long*)ei;
        s = (int)p[i]; d = (int)p[E + i];
    } else {
        const int* p = (const int*)ei;
        s = p[i]; d = p[E + i];
    }
}

// m16n8k16 bf16 mma, D==C accumulate
#define MMA_BF16(cr, a, b0, b1)                                            \
    asm volatile(                                                          \
        "mma.sync.aligned.m16n8k16.row.col.f32.bf16.bf16.f32 "             \
        "{%0,%1,%2,%3}, {%4,%5,%6,%7}, {%8,%9}, {%0,%1,%2,%3};"            \
        : "+f"((cr)[0]), "+f"((cr)[1]), "+f"((cr)[2]), "+f"((cr)[3])       \
        : "r"((a)[0]), "r"((a)[1]), "r"((a)[2]), "r"((a)[3]),              \
          "r"(b0), "r"(b1))

// split one float into bf16 hi + bf16(lo residual), as ushorts
__device__ __forceinline__ void bsplit(float v, unsigned short& h, unsigned short& l) {
    __nv_bfloat16 hb = __float2bfloat16(v);
    h = __bfloat16_as_ushort(hb);
    l = __bfloat16_as_ushort(__float2bfloat16(v - __bfloat162float(hb)));
}

// ---------------- launch 1: init + dtype detect + node forward ---------------
__global__ __launch_bounds__(256) void node_fwd_init(
    const float* __restrict__ x, const float* __restrict__ W1,
    const float* __restrict__ b1, const float* __restrict__ W2,
    const float* __restrict__ att_s, const float* __restrict__ att_d,
    const void* __restrict__ ei, int N)
{
    const int tid = threadIdx.x;
    const int gtid = blockIdx.x * 256 + tid;
    const int nthr = gridDim.x * 256;

    for (int i = gtid; i < MAXN * HID; i += nthr) g_S[i] = 0.0f;
    for (int i = gtid; i < MAXN; i += nthr) {
        g_den[i]  = (i < N) ? 0.0f : 1.0f;
        g_menc[i] = (int)0x80000000;
    }
    if (gtid == 0) {
        const long long* p = (const long long*)ei;
        int ok = 1;
        #pragma unroll
        for (int t = 0; t < 32; t++) {
            long long v = p[t];
            if (v < 0 || v >= (long long)N) ok = 0;
        }
        g_is64 = ok;
    }

    __shared__ float xs[32][IN_DIM];
    __shared__ float hs[32][EMB];
    __shared__ float zs[32][HID];
    const int r0 = blockIdx.x * 32;

    for (int i = tid; i < 32 * IN_DIM; i += 256) {
        int r = i / IN_DIM, c = i % IN_DIM;
        xs[r][c] = (r0 + r < N) ? x[(size_t)(r0 + r) * IN_DIM + c] : 0.0f;
    }
    __syncthreads();

    {
        int col = tid & 127;
        int rg  = tid >> 7;
        float acc[16];
        #pragma unroll
        for (int j = 0; j < 16; j++) acc[j] = 0.0f;
        for (int k = 0; k < IN_DIM; k++) {
            float w = W1[k * EMB + col];
            #pragma unroll
            for (int j = 0; j < 16; j++) acc[j] += xs[rg + 2 * j][k] * w;
        }
        float bb = b1[col];
        #pragma unroll
        for (int j = 0; j < 16; j++)
            hs[rg + 2 * j][col] = fmaxf(acc[j] + bb, 0.0f);
    }
    __syncthreads();

    {
        int col = tid & 63;
        int rg  = tid >> 6;
        float acc[8];
        #pragma unroll
        for (int j = 0; j < 8; j++) acc[j] = 0.0f;
        for (int k = 0; k < EMB; k++) {
            float w = W2[k * HID + col];
            #pragma unroll
            for (int j = 0; j < 8; j++) acc[j] += hs[rg + 4 * j][k] * w;
        }
        #pragma unroll
        for (int j = 0; j < 8; j++) {
            int r = rg + 4 * j;
            zs[r][col] = acc[j];
            if (r0 + r < N) g_z[(size_t)(r0 + r) * HID + col] = acc[j];
        }
    }
    __syncthreads();

    if (tid < 32) {
        int r = tid;
        if (r0 + r < N) {
            float s1 = 0.0f, s2 = 0.0f;
            #pragma unroll
            for (int k = 0; k < HID; k++) {
                float zv = zs[r][k];
                s1 += zv * att_s[k];
                s2 += zv * att_d[k];
            }
            g_asrc[r0 + r] = s1;
            g_adst[r0 + r] = s2;
        }
    }
}

// ---------------- launch 2: segment max --------------------------------------
__global__ void edge_max(const void* __restrict__ ei, int E, int N) {
    int i = blockIdx.x * blockDim.x + threadIdx.x;
    int ET = E + N;
    if (i >= ET) return;
    int s, d;
    edge_pair(ei, E, N, i, s, d);
    float e = g_asrc[s] + g_adst[d];
    e = e > 0.0f ? e : NEG * e;
    atomicMax(&g_menc[d], fenc(e));
}

// ---------------- launch 3: scatter (8 threads/edge, red.v4) ------------------
__global__ __launch_bounds__(256) void edge_scatter(
    const void* __restrict__ ei, int E, int N)
{
    int gid  = blockIdx.x * blockDim.x + threadIdx.x;
    int eidx = gid >> 3;
    int sub  = gid & 7;
    int ET = E + N;
    if (eidx >= ET) return;
    int s, d;
    edge_pair(ei, E, N, eidx, s, d);
    float e = g_asrc[s] + g_adst[d];
    e = e > 0.0f ? e : NEG * e;
    float ex = __expf(e - fdec(g_menc[d]));
    if (sub == 0) atomicAdd(&g_den[d], ex);

    const float4* zr = (const float4*)(g_z + (size_t)s * HID);
    float4 z1 = zr[sub];
    float4 z2 = zr[sub + 8];
    float* p1 = g_S + (size_t)d * HID + sub * 4;
    float* p2 = p1 + 32;
    asm volatile("red.global.add.v4.f32 [%0], {%1,%2,%3,%4};"
                 :: "l"(p1), "f"(ex * z1.x), "f"(ex * z1.y),
                    "f"(ex * z1.z), "f"(ex * z1.w) : "memory");
    asm volatile("red.global.add.v4.f32 [%0], {%1,%2,%3,%4};"
                 :: "l"(p2), "f"(ex * z2.x), "f"(ex * z2.y),
                    "f"(ex * z2.z), "f"(ex * z2.w) : "memory");
}

// ---------------- launch 4: sim = sigmoid(Z Z^T) via bf16-split mma ----------
// 128x128 tile per block, 8 warps each 64x32, K=64 staged once as bf16 hi/lo.
// 4 k-steps of m16n8k16; 3 MMAs (hh,hl,lh) per fragment pair.
#define LDW 36                                  // uint32 words per staged row
#define SIM_SMEM (4 * 128 * LDW * 4)            // Ah,Al,Bh,Bl = 73728 B

__global__ __launch_bounds__(256, 2) void sim_mma(
    float* __restrict__ out, const float* __restrict__ gat_b, int N)
{
    const int bi = blockIdx.y, bj = blockIdx.x;
    if (bi > bj) return;

    extern __shared__ float sm[];
    uint32* Ah = (uint32*)sm;
    uint32* Al = Ah + 128 * LDW;
    uint32* Bh = Ah + 2 * 128 * LDW;
    uint32* Bl = Ah + 3 * 128 * LDW;

    const int tid  = threadIdx.x;
    const int lane = tid & 31, wid = tid >> 5;
    const int g = lane >> 2, t = lane & 3;
    const int wrow = (wid & 1) * 64;
    const int wcol = (wid >> 1) * 32;
    const int i0 = bi * 128, j0 = bj * 128;

    // ---- fill: load S, normalize, bf16 hi/lo split, pack bf16x2 words ----
    #pragma unroll
    for (int it = 0; it < 16; it++) {
        int idx  = tid + it * 256;          // 0..4095
        int side = idx >> 11;               // 0 = A (i0 rows), 1 = B (j0 rows)
        int rem  = idx & 2047;
        int row  = rem >> 4;                // 0..127
        int q    = rem & 15;                // float4 index within 64-float row
        int grow = (side ? j0 : i0) + row;
        float4 sv = *(const float4*)(g_S + (size_t)grow * HID + q * 4);
        float  rd = __fdividef(1.0f, g_den[grow]);
        float4 bb = *(const float4*)(gat_b + q * 4);
        float v0 = sv.x * rd + bb.x;
        float v1 = sv.y * rd + bb.y;
        float v2 = sv.z * rd + bb.z;
        float v3 = sv.w * rd + bb.w;
        unsigned short h0, h1, h2, h3, l0, l1, l2, l3;
        bsplit(v0, h0, l0); bsplit(v1, h1, l1);
        bsplit(v2, h2, l2); bsplit(v3, h3, l3);
        uint32* H = side ? Bh : Ah;
        uint32* L = side ? Bl : Al;
        int w = row * LDW + 2 * q;
        H[w]     = ((uint32)h1 << 16) | h0;
        H[w + 1] = ((uint32)h3 << 16) | h2;
        L[w]     = ((uint32)l1 << 16) | l0;
        L[w + 1] = ((uint32)l3 << 16) | l2;
    }
    __syncthreads();

    float c[4][4][4];
    #pragma unroll
    for (int mt = 0; mt < 4; mt++)
        #pragma unroll
        for (int nt = 0; nt < 4; nt++)
            #pragma unroll
            for (int e = 0; e < 4; e++) c[mt][nt][e] = 0.0f;

    // ---- mainloop: 4 k-steps of 16 ----
    #pragma unroll
    for (int ks = 0; ks < 4; ks++) {
        uint32 ah[4][4], al[4][4];
        #pragma unroll
        for (int mt = 0; mt < 4; mt++) {
            int ra = (wrow + mt * 16 + g) * LDW + ks * 8 + t;
            ah[mt][0] = Ah[ra];
            ah[mt][1] = Ah[ra + 8 * LDW];
            ah[mt][2] = Ah[ra + 4];
            ah[mt][3] = Ah[ra + 8 * LDW + 4];
            al[mt][0] = Al[ra];
            al[mt][1] = Al[ra + 8 * LDW];
            al[mt][2] = Al[ra + 4];
            al[mt][3] = Al[ra + 8 * LDW + 4];
        }
        #pragma unroll
        for (int nt = 0; nt < 4; nt++) {
            int rb = (wcol + nt * 8 + g) * LDW + ks * 8 + t;
            uint32 bh0 = Bh[rb], bh1 = Bh[rb + 4];
            uint32 bl0 = Bl[rb], bl1 = Bl[rb + 4];
            #pragma unroll
            for (int mt = 0; mt < 4; mt++) {
                MMA_BF16(c[mt][nt], ah[mt], bh0, bh1);
                MMA_BF16(c[mt][nt], ah[mt], bl0, bl1);
                MMA_BF16(c[mt][nt], al[mt], bh0, bh1);
            }
        }
    }
    __syncthreads();

    // ---- epilogue: sigmoid -> stage (reuses smem) -> coalesced dual write ----
    float* stage = sm;   // 128 x 132 floats = 67584 B < SIM_SMEM
    #pragma unroll
    for (int mt = 0; mt < 4; mt++)
        #pragma unroll
        for (int nt = 0; nt < 4; nt++) {
            int rs = wrow + mt * 16 + g;
            int cs = wcol + nt * 8 + 2 * t;
            stage[rs * 132 + cs]           = sigm(c[mt][nt][0]);
            stage[rs * 132 + cs + 1]       = sigm(c[mt][nt][1]);
            stage[(rs + 8) * 132 + cs]     = sigm(c[mt][nt][2]);
            stage[(rs + 8) * 132 + cs + 1] = sigm(c[mt][nt][3]);
        }
    __syncthreads();

    // straight tile
    for (int it = tid; it < 128 * 32; it += 256) {
        int row = it >> 5, cq = it & 31;
        int gi = i0 + row, gj = j0 + cq * 4;
        if (gi >= N || gj >= N) continue;
        const float* sp = stage + row * 132 + cq * 4;
        if (gj + 3 < N) {
            *(float4*)(out + (size_t)gi * N + gj) =
                make_float4(sp[0], sp[1], sp[2], sp[3]);
        } else {
            #pragma unroll
            for (int e = 0; e < 4; e++)
                if (gj + e < N) out[(size_t)gi * N + gj + e] = sp[e];
        }
    }
    // transposed tile
    if (bi != bj) {
        for (int it = tid; it < 128 * 32; it += 256) {
            int crow = it >> 5, rq = it & 31;
            int gi = j0 + crow, gj = i0 + rq * 4;
            if (gi >= N || gj >= N) continue;
            float4 v = make_float4(stage[(rq * 4 + 0) * 132 + crow],
                                   stage[(rq * 4 + 1) * 132 + crow],
                                   stage[(rq * 4 + 2) * 132 + crow],
                                   stage[(rq * 4 + 3) * 132 + crow]);
            if (gj + 3 < N) {
                *(float4*)(out + (size_t)gi * N + gj) = v;
            } else {
                const float vv[4] = {v.x, v.y, v.z, v.w};
                #pragma unroll
                for (int e = 0; e < 4; e++)
                    if (gj + e < N) out[(size_t)gi * N + gj + e] = vv[e];
            }
        }
    }
}

// ---------------- launch 5: embed output tail ---------------------------------
__global__ void copy_embed(float* __restrict__ out_embed,
                           const float* __restrict__ gat_b, int N)
{
    int i = blockIdx.x * blockDim.x + threadIdx.x;
    if (i >= N * HID) return;
    int n = i >> 6, f = i & 63;
    out_embed[i] = g_S[i] / g_den[n] + gat_b[f];
}

// ---------------- launch --------------------------------------------------------
extern "C" void kernel_launch(void* const* d_in, const int* in_sizes, int n_in,
                              void* d_out, int out_size)
{
    const float* x    = (const float*)d_in[0];
    const void*  ei   = d_in[1];
    const float* W1   = (const float*)d_in[2];
    const float* b1   = (const float*)d_in[3];
    const float* W2   = (const float*)d_in[4];
    const float* atts = (const float*)d_in[5];
    const float* attd = (const float*)d_in[6];
    const float* gb   = (const float*)d_in[7];

    const int N = in_sizes[0] / IN_DIM;
    const int E = in_sizes[1] / 2;
    const int ET = E + N;

    float* out = (float*)d_out;

    static int smem_set = 0;
    if (!smem_set) {
        cudaFuncSetAttribute(sim_mma, cudaFuncAttributeMaxDynamicSharedMemorySize,
                             SIM_SMEM);
        smem_set = 1;
    }

    node_fwd_init<<<(N + 31) / 32, 256>>>(x, W1, b1, W2, atts, attd, ei, N); // 1
    edge_max<<<(ET + 255) / 256, 256>>>(ei, E, N);                           // 2
    edge_scatter<<<(ET * 8 + 255) / 256, 256>>>(ei, E, N);                   // 3

    const int nt = (N + 127) / 128;
    dim3 grid(nt, nt);
    sim_mma<<<grid, 256, SIM_SMEM>>>(out, gb, N);                            // 4

    if ((size_t)out_size >= (size_t)N * N + (size_t)N * HID) {
        copy_embed<<<(N * HID + 255) / 256, 256>>>(out + (size_t)N * N, gb, N); // 5
    }
}

// round 8
// speedup vs baseline: 1.3606x; 1.1236x over previous
#include <cuda_runtime.h>
#include <cuda_bf16.h>
#include <math.h>
#include <stdint.h>

#define IN_DIM 128
#define EMB    128
#define HID    64
#define NEG    0.2f
#define MAXN   10240   // padded

typedef unsigned int uint32;

// ---------------- scratch (static device globals; no allocation) ------------
__device__ float g_z[MAXN * HID];
__device__ float g_S[MAXN * HID];
__device__ float g_asrc[MAXN];
__device__ float g_adst[MAXN];
__device__ int   g_menc[MAXN];
__device__ float g_den[MAXN];
__device__ int   g_is64;

// ---------------- small helpers ---------------------------------------------
__device__ __forceinline__ int fenc(float f) {
    int b = __float_as_int(f);
    return b >= 0 ? b : (b ^ 0x7fffffff);
}
__device__ __forceinline__ float fdec(int e) {
    return __int_as_float(e >= 0 ? e : (e ^ 0x7fffffff));
}
__device__ __forceinline__ float sigm(float v) {
    return __fdividef(1.0f, 1.0f + __expf(-v));
}
__device__ __forceinline__ void edge_pair(const void* ei, int E, int N, int i,
                                          int& s, int& d)
{
    if (i >= E) { s = d = i - E; return; }
    if (g_is64) {
        const long long* p = (const long long*)ei;
        s = (int)p[i]; d = (int)p[E + i];
    } else {
        const int* p = (const int*)ei;
        s = p[i]; d = p[E + i];
    }
}

// m16n8k16 bf16 mma, D==C accumulate
#define MMA_BF16(cr, a, b0, b1)                                            \
    asm volatile(                                                          \
        "mma.sync.aligned.m16n8k16.row.col.f32.bf16.bf16.f32 "             \
        "{%0,%1,%2,%3}, {%4,%5,%6,%7}, {%8,%9}, {%0,%1,%2,%3};"            \
        : "+f"((cr)[0]), "+f"((cr)[1]), "+f"((cr)[2]), "+f"((cr)[3])       \
        : "r"((a)[0]), "r"((a)[1]), "r"((a)[2]), "r"((a)[3]),              \
          "r"(b0), "r"(b1))

#define LDSM_X4(r, addr)                                                   \
    asm volatile(                                                          \
        "ldmatrix.sync.aligned.m8n8.x4.shared.b16 {%0,%1,%2,%3}, [%4];"    \
        : "=r"((r)[0]), "=r"((r)[1]), "=r"((r)[2]), "=r"((r)[3])           \
        : "r"(addr))

// split one float into bf16 hi + bf16(lo residual), as ushorts
__device__ __forceinline__ void bsplit(float v, unsigned short& h, unsigned short& l) {
    __nv_bfloat16 hb = __float2bfloat16(v);
    h = __bfloat16_as_ushort(hb);
    l = __bfloat16_as_ushort(__float2bfloat16(v - __bfloat162float(hb)));
}

__device__ __forceinline__ uint32 smem_u32(const void* p) {
    uint32 a;
    asm("{ .reg .u64 t; cvta.to.shared.u64 t, %1; cvt.u32.u64 %0, t; }"
        : "=r"(a) : "l"(p));
    return a;
}

// ---------------- launch 1: init + dtype detect + node forward ---------------
__global__ __launch_bounds__(256) void node_fwd_init(
    const float* __restrict__ x, const float* __restrict__ W1,
    const float* __restrict__ b1, const float* __restrict__ W2,
    const float* __restrict__ att_s, const float* __restrict__ att_d,
    const void* __restrict__ ei, int N)
{
    const int tid = threadIdx.x;
    const int gtid = blockIdx.x * 256 + tid;
    const int nthr = gridDim.x * 256;

    for (int i = gtid; i < MAXN * HID; i += nthr) g_S[i] = 0.0f;
    for (int i = gtid; i < MAXN; i += nthr) {
        g_den[i]  = (i < N) ? 0.0f : 1.0f;
        g_menc[i] = (int)0x80000000;
    }
    if (gtid == 0) {
        const long long* p = (const long long*)ei;
        int ok = 1;
        #pragma unroll
        for (int t = 0; t < 32; t++) {
            long long v = p[t];
            if (v < 0 || v >= (long long)N) ok = 0;
        }
        g_is64 = ok;
    }

    __shared__ float xs[32][IN_DIM];
    __shared__ float hs[32][EMB];
    __shared__ float zs[32][HID];
    const int r0 = blockIdx.x * 32;

    for (int i = tid; i < 32 * IN_DIM; i += 256) {
        int r = i / IN_DIM, c = i % IN_DIM;
        xs[r][c] = (r0 + r < N) ? x[(size_t)(r0 + r) * IN_DIM + c] : 0.0f;
    }
    __syncthreads();

    {
        int col = tid & 127;
        int rg  = tid >> 7;
        float acc[16];
        #pragma unroll
        for (int j = 0; j < 16; j++) acc[j] = 0.0f;
        for (int k = 0; k < IN_DIM; k++) {
            float w = W1[k * EMB + col];
            #pragma unroll
            for (int j = 0; j < 16; j++) acc[j] += xs[rg + 2 * j][k] * w;
        }
        float bb = b1[col];
        #pragma unroll
        for (int j = 0; j < 16; j++)
            hs[rg + 2 * j][col] = fmaxf(acc[j] + bb, 0.0f);
    }
    __syncthreads();

    {
        int col = tid & 63;
        int rg  = tid >> 6;
        float acc[8];
        #pragma unroll
        for (int j = 0; j < 8; j++) acc[j] = 0.0f;
        for (int k = 0; k < EMB; k++) {
            float w = W2[k * HID + col];
            #pragma unroll
            for (int j = 0; j < 8; j++) acc[j] += hs[rg + 4 * j][k] * w;
        }
        #pragma unroll
        for (int j = 0; j < 8; j++) {
            int r = rg + 4 * j;
            zs[r][col] = acc[j];
            if (r0 + r < N) g_z[(size_t)(r0 + r) * HID + col] = acc[j];
        }
    }
    __syncthreads();

    if (tid < 32) {
        int r = tid;
        if (r0 + r < N) {
            float s1 = 0.0f, s2 = 0.0f;
            #pragma unroll
            for (int k = 0; k < HID; k++) {
                float zv = zs[r][k];
                s1 += zv * att_s[k];
                s2 += zv * att_d[k];
            }
            g_asrc[r0 + r] = s1;
            g_adst[r0 + r] = s2;
        }
    }
}

// ---------------- launch 2: segment max --------------------------------------
__global__ void edge_max(const void* __restrict__ ei, int E, int N) {
    int i = blockIdx.x * blockDim.x + threadIdx.x;
    int ET = E + N;
    if (i >= ET) return;
    int s, d;
    edge_pair(ei, E, N, i, s, d);
    float e = g_asrc[s] + g_adst[d];
    e = e > 0.0f ? e : NEG * e;
    atomicMax(&g_menc[d], fenc(e));
}

// ---------------- launch 3: scatter (8 threads/edge, red.v4) ------------------
__global__ __launch_bounds__(256) void edge_scatter(
    const void* __restrict__ ei, int E, int N)
{
    int gid  = blockIdx.x * blockDim.x + threadIdx.x;
    int eidx = gid >> 3;
    int sub  = gid & 7;
    int ET = E + N;
    if (eidx >= ET) return;
    int s, d;
    edge_pair(ei, E, N, eidx, s, d);
    float e = g_asrc[s] + g_adst[d];
    e = e > 0.0f ? e : NEG * e;
    float ex = __expf(e - fdec(g_menc[d]));
    if (sub == 0) atomicAdd(&g_den[d], ex);

    const float4* zr = (const float4*)(g_z + (size_t)s * HID);
    float4 z1 = zr[sub];
    float4 z2 = zr[sub + 8];
    float* p1 = g_S + (size_t)d * HID + sub * 4;
    float* p2 = p1 + 32;
    asm volatile("red.global.add.v4.f32 [%0], {%1,%2,%3,%4};"
                 :: "l"(p1), "f"(ex * z1.x), "f"(ex * z1.y),
                    "f"(ex * z1.z), "f"(ex * z1.w) : "memory");
    asm volatile("red.global.add.v4.f32 [%0], {%1,%2,%3,%4};"
                 :: "l"(p2), "f"(ex * z2.x), "f"(ex * z2.y),
                    "f"(ex * z2.z), "f"(ex * z2.w) : "memory");
}

// ---------------- launch 4: sim = sigmoid(Z Z^T) via bf16-split mma ----------
// 128x128 tile, 8 warps each 64x32, K=64 staged once as bf16 hi/lo.
// Fragments fed by ldmatrix.x4; straight tile stored direct from registers;
// transposed tile via conflict-free smem stage.
#define LDW 36                                  // uint32 words per staged row
#define SIM_SMEM (4 * 128 * LDW * 4)            // Ah,Al,Bh,Bl = 73728 B
#define AL_OFF (128 * LDW * 4)                  // byte offset Ah->Al (and Bh->Bl)
#define SS 132                                  // stage row stride (floats)

__global__ __launch_bounds__(256, 2) void sim_mma(
    float* __restrict__ out, const float* __restrict__ gat_b, int N)
{
    const int bi = blockIdx.y, bj = blockIdx.x;
    if (bi > bj) return;

    extern __shared__ float sm[];
    uint32* Ah = (uint32*)sm;
    uint32* Bh = Ah + 2 * 128 * LDW;

    const int tid  = threadIdx.x;
    const int lane = tid & 31, wid = tid >> 5;
    const int g = lane >> 2, t = lane & 3;
    const int wrow = (wid & 1) * 64;
    const int wcol = (wid >> 1) * 32;
    const int i0 = bi * 128, j0 = bj * 128;

    // ---- fill: load S, normalize, bf16 hi/lo split, pack bf16x2 words ----
    #pragma unroll
    for (int it = 0; it < 16; it++) {
        int idx  = tid + it * 256;          // 0..4095
        int side = idx >> 11;               // 0 = A (i0 rows), 1 = B (j0 rows)
        int rem  = idx & 2047;
        int row  = rem >> 4;                // 0..127
        int q    = rem & 15;                // float4 index within 64-float row
        int grow = (side ? j0 : i0) + row;
        float4 sv = *(const float4*)(g_S + (size_t)grow * HID + q * 4);
        float  rd = __fdividef(1.0f, g_den[grow]);
        float4 bb = *(const float4*)(gat_b + q * 4);
        float v0 = sv.x * rd + bb.x;
        float v1 = sv.y * rd + bb.y;
        float v2 = sv.z * rd + bb.z;
        float v3 = sv.w * rd + bb.w;
        unsigned short h0, h1, h2, h3, l0, l1, l2, l3;
        bsplit(v0, h0, l0); bsplit(v1, h1, l1);
        bsplit(v2, h2, l2); bsplit(v3, h3, l3);
        uint32* H = side ? Bh : Ah;
        int w = row * LDW + 2 * q;
        H[w]                 = ((uint32)h1 << 16) | h0;
        H[w + 1]             = ((uint32)h3 << 16) | h2;
        H[w + 128 * LDW]     = ((uint32)l1 << 16) | l0;
        H[w + 1 + 128 * LDW] = ((uint32)l3 << 16) | l2;
    }
    __syncthreads();

    float c[4][4][4];
    #pragma unroll
    for (int mt = 0; mt < 4; mt++)
        #pragma unroll
        for (int nt = 0; nt < 4; nt++)
            #pragma unroll
            for (int e = 0; e < 4; e++) c[mt][nt][e] = 0.0f;

    // ---- per-lane ldmatrix base addresses (bytes, shared space) ----
    const uint32 sbA = smem_u32(Ah);
    const uint32 sbB = smem_u32(Bh);
    uint32 aAddr[4], bAddr[2];
    {
        int rA = (lane & 7) + (lane & 8);          // row-in-16 for A tiles
        int kA = (lane >> 4) * 4;                  // +4 words for k8-15 tiles
        #pragma unroll
        for (int mt = 0; mt < 4; mt++)
            aAddr[mt] = sbA + (uint32)(((wrow + mt * 16 + rA) * LDW + kA) * 4);
        int rB = (lane & 7) + ((lane & 16) >> 1);  // tiles 2,3 -> rows +8
        int kB = ((lane >> 3) & 1) * 4;            // tiles 1,3 -> k words +4
        #pragma unroll
        for (int p = 0; p < 2; p++)
            bAddr[p] = sbB + (uint32)(((wcol + p * 16 + rB) * LDW + kB) * 4);
    }

    // ---- mainloop: 4 k-steps of 16 ----
    #pragma unroll
    for (int ks = 0; ks < 4; ks++) {
        uint32 bh[2][4], bl[2][4];
        #pragma unroll
        for (int p = 0; p < 2; p++) {
            LDSM_X4(bh[p], bAddr[p]);
            LDSM_X4(bl[p], bAddr[p] + AL_OFF);
            bAddr[p] += 32;
        }
        #pragma unroll
        for (int mt = 0; mt < 4; mt++) {
            uint32 ah[4], al[4];
            LDSM_X4(ah, aAddr[mt]);
            LDSM_X4(al, aAddr[mt] + AL_OFF);
            aAddr[mt] += 32;
            #pragma unroll
            for (int nt = 0; nt < 4; nt++) {
                int p = nt >> 1, o = (nt & 1) * 2;
                uint32 b0h = bh[p][o], b1h = bh[p][o + 1];
                uint32 b0l = bl[p][o], b1l = bl[p][o + 1];
                MMA_BF16(c[mt][nt], ah, b0h, b1h);
                MMA_BF16(c[mt][nt], ah, b0l, b1l);
                MMA_BF16(c[mt][nt], al, b0h, b1h);
            }
        }
    }
    __syncthreads();

    // ---- epilogue ----
    float* stage = sm;   // 128 x SS floats = 67584 B < SIM_SMEM
    const bool diag = (bi == bj);

    #pragma unroll
    for (int mt = 0; mt < 4; mt++)
        #pragma unroll
        for (int nt = 0; nt < 4; nt++) {
            int rs = wrow + mt * 16 + g;
            int cs = wcol + nt * 8 + 2 * t;
            float s0 = sigm(c[mt][nt][0]);
            float s1 = sigm(c[mt][nt][1]);
            float s2 = sigm(c[mt][nt][2]);
            float s3 = sigm(c[mt][nt][3]);

            // straight tile: direct from registers (4 lanes = one 32B sector)
            int gj = j0 + cs;
            int gi = i0 + rs;
            if (gi < N) {
                if (gj + 1 < N)      *(float2*)(out + (size_t)gi * N + gj) = make_float2(s0, s1);
                else if (gj < N)     out[(size_t)gi * N + gj] = s0;
            }
            int gi2 = gi + 8;
            if (gi2 < N) {
                if (gj + 1 < N)      *(float2*)(out + (size_t)gi2 * N + gj) = make_float2(s2, s3);
                else if (gj < N)     out[(size_t)gi2 * N + gj] = s2;
            }

            // stage for transposed write
            if (!diag) {
                *(float2*)&stage[rs * SS + cs]       = make_float2(s0, s1);
                *(float2*)&stage[(rs + 8) * SS + cs] = make_float2(s2, s3);
            }
        }

    if (!diag) {
        __syncthreads();
        // transposed tile: warp reads stage rows (col = lane, conflict-free),
        // stores 32B contiguous per output row.
        const int cbase = (wid & 3) * 32;          // 4 warps cover 128 cols
        const int rhalf = wid >> 2;                // 2 row groups
        int ci = cbase + lane;
        int gi_t = j0 + ci;
        bool rowok = (gi_t < N);
        #pragma unroll
        for (int itr = 0; itr < 8; itr++) {
            int rq = rhalf + itr * 2;              // 0..15
            int r8 = rq * 8;
            float v[8];
            #pragma unroll
            for (int e = 0; e < 8; e++)
                v[e] = stage[(r8 + e) * SS + ci];
            if (!rowok) continue;
            int gj = i0 + r8;
            float* orow = out + (size_t)gi_t * N + gj;
            if (gj + 7 < N) {
                *(float4*)orow       = make_float4(v[0], v[1], v[2], v[3]);
                *(float4*)(orow + 4) = make_float4(v[4], v[5], v[6], v[7]);
            } else {
                #pragma unroll
                for (int e = 0; e < 8; e++)
                    if (gj + e < N) orow[e] = v[e];
            }
        }
    }
}

// ---------------- launch 5: embed output tail ---------------------------------
__global__ void copy_embed(float* __restrict__ out_embed,
                           const float* __restrict__ gat_b, int N)
{
    int i = blockIdx.x * blockDim.x + threadIdx.x;
    if (i >= N * HID) return;
    int n = i >> 6, f = i & 63;
    out_embed[i] = g_S[i] / g_den[n] + gat_b[f];
}

// ---------------- launch --------------------------------------------------------
extern "C" void kernel_launch(void* const* d_in, const int* in_sizes, int n_in,
                              void* d_out, int out_size)
{
    const float* x    = (const float*)d_in[0];
    const void*  ei   = d_in[1];
    const float* W1   = (const float*)d_in[2];
    const float* b1   = (const float*)d_in[3];
    const float* W2   = (const float*)d_in[4];
    const float* atts = (const float*)d_in[5];
    const float* attd = (const float*)d_in[6];
    const float* gb   = (const float*)d_in[7];

    const int N = in_sizes[0] / IN_DIM;
    const int E = in_sizes[1] / 2;
    const int ET = E + N;

    float* out = (float*)d_out;

    static int smem_set = 0;
    if (!smem_set) {
        cudaFuncSetAttribute(sim_mma, cudaFuncAttributeMaxDynamicSharedMemorySize,
                             SIM_SMEM);
        smem_set = 1;
    }

    node_fwd_init<<<(N + 31) / 32, 256>>>(x, W1, b1, W2, atts, attd, ei, N); // 1
    edge_max<<<(ET + 255) / 256, 256>>>(ei, E, N);                           // 2
    edge_scatter<<<(ET * 8 + 255) / 256, 256>>>(ei, E, N);                   // 3

    const int nt = (N + 127) / 128;
    dim3 grid(nt, nt);
    sim_mma<<<grid, 256, SIM_SMEM>>>(out, gb, N);                            // 4

    if ((size_t)out_size >= (size_t)N * N + (size_t)N * HID) {
        copy_embed<<<(N * HID + 255) / 256, 256>>>(out + (size_t)N * N, gb, N); // 5
    }
}

// round 9
// speedup vs baseline: 1.4131x; 1.0386x over previous
#include <cuda_runtime.h>
#include <cuda_bf16.h>
#include <math.h>
#include <stdint.h>

#define IN_DIM 128
#define EMB    128
#define HID    64
#define NEG    0.2f
#define MAXN   10240   // padded

typedef unsigned int uint32;

// ---------------- scratch (static device globals; no allocation) ------------
__device__ float g_z[MAXN * HID];
__device__ float g_S[MAXN * HID];
__device__ unsigned short g_zh[MAXN * HID];   // bf16 hi plane, 128B rows
__device__ unsigned short g_zl[MAXN * HID];   // bf16 lo plane, 128B rows
__device__ float g_asrc[MAXN];
__device__ float g_adst[MAXN];
__device__ int   g_menc[MAXN];
__device__ float g_den[MAXN];
__device__ int   g_is64;

// ---------------- small helpers ---------------------------------------------
__device__ __forceinline__ int fenc(float f) {
    int b = __float_as_int(f);
    return b >= 0 ? b : (b ^ 0x7fffffff);
}
__device__ __forceinline__ float fdec(int e) {
    return __int_as_float(e >= 0 ? e : (e ^ 0x7fffffff));
}
__device__ __forceinline__ float sigm(float v) {
    return __fdividef(1.0f, 1.0f + __expf(-v));
}
__device__ __forceinline__ void edge_pair(const void* ei, int E, int N, int i,
                                          int& s, int& d)
{
    if (i >= E) { s = d = i - E; return; }
    if (g_is64) {
        const long long* p = (const long long*)ei;
        s = (int)p[i]; d = (int)p[E + i];
    } else {
        const int* p = (const int*)ei;
        s = p[i]; d = p[E + i];
    }
}

// m16n8k16 bf16 mma, D==C accumulate
#define MMA_BF16(cr, a, b0, b1)                                            \
    asm volatile(                                                          \
        "mma.sync.aligned.m16n8k16.row.col.f32.bf16.bf16.f32 "             \
        "{%0,%1,%2,%3}, {%4,%5,%6,%7}, {%8,%9}, {%0,%1,%2,%3};"            \
        : "+f"((cr)[0]), "+f"((cr)[1]), "+f"((cr)[2]), "+f"((cr)[3])       \
        : "r"((a)[0]), "r"((a)[1]), "r"((a)[2]), "r"((a)[3]),              \
          "r"(b0), "r"(b1))

#define LDSM_X4(r, addr)                                                   \
    asm volatile(                                                          \
        "ldmatrix.sync.aligned.m8n8.x4.shared.b16 {%0,%1,%2,%3}, [%4];"    \
        : "=r"((r)[0]), "=r"((r)[1]), "=r"((r)[2]), "=r"((r)[3])           \
        : "r"(addr))

#define CP_ASYNC16(dst, src)                                               \
    asm volatile("cp.async.cg.shared.global [%0], [%1], 16;"               \
                 :: "r"(dst), "l"(src) : "memory")

// split one float into bf16 hi + bf16(lo residual), as ushorts
__device__ __forceinline__ void bsplit(float v, unsigned short& h, unsigned short& l) {
    __nv_bfloat16 hb = __float2bfloat16(v);
    h = __bfloat16_as_ushort(hb);
    l = __bfloat16_as_ushort(__float2bfloat16(v - __bfloat162float(hb)));
}

__device__ __forceinline__ uint32 smem_u32(const void* p) {
    uint32 a;
    asm("{ .reg .u64 t; cvta.to.shared.u64 t, %1; cvt.u32.u64 %0, t; }"
        : "=r"(a) : "l"(p));
    return a;
}

// ---------------- launch 1: init + dtype detect + node forward ---------------
__global__ __launch_bounds__(256) void node_fwd_init(
    const float* __restrict__ x, const float* __restrict__ W1,
    const float* __restrict__ b1, const float* __restrict__ W2,
    const float* __restrict__ att_s, const float* __restrict__ att_d,
    const void* __restrict__ ei, int N)
{
    const int tid = threadIdx.x;
    const int gtid = blockIdx.x * 256 + tid;
    const int nthr = gridDim.x * 256;

    for (int i = gtid; i < MAXN * HID; i += nthr) g_S[i] = 0.0f;
    for (int i = gtid; i < MAXN; i += nthr) {
        g_den[i]  = (i < N) ? 0.0f : 1.0f;
        g_menc[i] = (int)0x80000000;
    }
    if (gtid == 0) {
        const long long* p = (const long long*)ei;
        int ok = 1;
        #pragma unroll
        for (int t = 0; t < 32; t++) {
            long long v = p[t];
            if (v < 0 || v >= (long long)N) ok = 0;
        }
        g_is64 = ok;
    }

    __shared__ float xs[32][IN_DIM];
    __shared__ float hs[32][EMB];
    __shared__ float zs[32][HID];
    const int r0 = blockIdx.x * 32;

    for (int i = tid; i < 32 * IN_DIM; i += 256) {
        int r = i / IN_DIM, c = i % IN_DIM;
        xs[r][c] = (r0 + r < N) ? x[(size_t)(r0 + r) * IN_DIM + c] : 0.0f;
    }
    __syncthreads();

    {
        int col = tid & 127;
        int rg  = tid >> 7;
        float acc[16];
        #pragma unroll
        for (int j = 0; j < 16; j++) acc[j] = 0.0f;
        for (int k = 0; k < IN_DIM; k++) {
            float w = W1[k * EMB + col];
            #pragma unroll
            for (int j = 0; j < 16; j++) acc[j] += xs[rg + 2 * j][k] * w;
        }
        float bb = b1[col];
        #pragma unroll
        for (int j = 0; j < 16; j++)
            hs[rg + 2 * j][col] = fmaxf(acc[j] + bb, 0.0f);
    }
    __syncthreads();

    {
        int col = tid & 63;
        int rg  = tid >> 6;
        float acc[8];
        #pragma unroll
        for (int j = 0; j < 8; j++) acc[j] = 0.0f;
        for (int k = 0; k < EMB; k++) {
            float w = W2[k * HID + col];
            #pragma unroll
            for (int j = 0; j < 8; j++) acc[j] += hs[rg + 4 * j][k] * w;
        }
        #pragma unroll
        for (int j = 0; j < 8; j++) {
            int r = rg + 4 * j;
            zs[r][col] = acc[j];
            if (r0 + r < N) g_z[(size_t)(r0 + r) * HID + col] = acc[j];
        }
    }
    __syncthreads();

    if (tid < 32) {
        int r = tid;
        if (r0 + r < N) {
            float s1 = 0.0f, s2 = 0.0f;
            #pragma unroll
            for (int k = 0; k < HID; k++) {
                float zv = zs[r][k];
                s1 += zv * att_s[k];
                s2 += zv * att_d[k];
            }
            g_asrc[r0 + r] = s1;
            g_adst[r0 + r] = s2;
        }
    }
}

// ---------------- launch 2: segment max --------------------------------------
__global__ void edge_max(const void* __restrict__ ei, int E, int N) {
    int i = blockIdx.x * blockDim.x + threadIdx.x;
    int ET = E + N;
    if (i >= ET) return;
    int s, d;
    edge_pair(ei, E, N, i, s, d);
    float e = g_asrc[s] + g_adst[d];
    e = e > 0.0f ? e : NEG * e;
    atomicMax(&g_menc[d], fenc(e));
}

// ---------------- launch 3: scatter (8 threads/edge, red.v4) ------------------
__global__ __launch_bounds__(256) void edge_scatter(
    const void* __restrict__ ei, int E, int N)
{
    int gid  = blockIdx.x * blockDim.x + threadIdx.x;
    int eidx = gid >> 3;
    int sub  = gid & 7;
    int ET = E + N;
    if (eidx >= ET) return;
    int s, d;
    edge_pair(ei, E, N, eidx, s, d);
    float e = g_asrc[s] + g_adst[d];
    e = e > 0.0f ? e : NEG * e;
    float ex = __expf(e - fdec(g_menc[d]));
    if (sub == 0) atomicAdd(&g_den[d], ex);

    const float4* zr = (const float4*)(g_z + (size_t)s * HID);
    float4 z1 = zr[sub];
    float4 z2 = zr[sub + 8];
    float* p1 = g_S + (size_t)d * HID + sub * 4;
    float* p2 = p1 + 32;
    asm volatile("red.global.add.v4.f32 [%0], {%1,%2,%3,%4};"
                 :: "l"(p1), "f"(ex * z1.x), "f"(ex * z1.y),
                    "f"(ex * z1.z), "f"(ex * z1.w) : "memory");
    asm volatile("red.global.add.v4.f32 [%0], {%1,%2,%3,%4};"
                 :: "l"(p2), "f"(ex * z2.x), "f"(ex * z2.y),
                    "f"(ex * z2.z), "f"(ex * z2.w) : "memory");
}

// ---------------- launch 4: finalize embed + bf16 split (+ embed tail) --------
__global__ void finalize_embed(const float* __restrict__ gat_b,
                               float* __restrict__ out_embed, int N)
{
    int i = blockIdx.x * blockDim.x + threadIdx.x;
    if (i >= MAXN * HID) return;
    int n = i >> 6, f = i & 63;
    float v = 0.0f;
    if (n < N) v = g_S[i] / g_den[n] + gat_b[f];
    unsigned short h, l;
    bsplit(v, h, l);
    g_zh[i] = h;
    g_zl[i] = l;
    if (out_embed != nullptr && n < N) out_embed[i] = v;
}

// ---------------- launch 5: sim = sigmoid(Z Z^T) via bf16-split mma ----------
// 128x128 tile, triangular 1-D grid, cp.async fill of precomputed hi/lo planes,
// ldmatrix fragment feed, 3-term (hh,hl,lh) accumulation.
#define LDW 36                                  // uint32 words per staged row
#define ROWB (LDW * 4)                          // 144 bytes per staged row
#define PLANE (128 * ROWB)                      // 18432 B per plane
#define SIM_SMEM (4 * PLANE)                    // 73728 B
#define AL_OFF PLANE                            // byte offset Ah->Al (Bh->Bl)
#define SS 132                                  // stage row stride (floats)

__global__ __launch_bounds__(256, 2) void sim_mma(
    float* __restrict__ out, int N, int nt)
{
    // ---- triangular block decode: blockIdx.x -> (bi <= bj) ----
    int kk = blockIdx.x;
    int bi;
    {
        float tnp = 2.0f * nt + 1.0f;
        bi = (int)((tnp - sqrtf(tnp * tnp - 8.0f * (float)kk)) * 0.5f);
        if (bi < 0) bi = 0;
        while ((bi + 1) * nt - ((bi + 1) * bi) / 2 <= kk) bi++;
        while (bi * nt - (bi * (bi - 1)) / 2 > kk) bi--;
    }
    const int bj = bi + (kk - (bi * nt - (bi * (bi - 1)) / 2));

    extern __shared__ float sm[];
    uint32* Ah = (uint32*)sm;
    uint32* Bh = Ah + 2 * 128 * LDW;

    const int tid  = threadIdx.x;
    const int lane = tid & 31, wid = tid >> 5;
    const int g = lane >> 2, t = lane & 3;
    const int wrow = (wid & 1) * 64;
    const int wcol = (wid >> 1) * 32;
    const int i0 = bi * 128, j0 = bj * 128;

    // ---- fill: pure cp.async 16B copies from precomputed hi/lo planes ----
    {
        const uint32 sb = smem_u32(sm);
        const char* srcs[4] = {
            (const char*)g_zh + (size_t)i0 * 128,
            (const char*)g_zl + (size_t)i0 * 128,
            (const char*)g_zh + (size_t)j0 * 128,
            (const char*)g_zl + (size_t)j0 * 128
        };
        #pragma unroll
        for (int it = 0; it < 16; it++) {
            int idx = tid + it * 256;        // 0..4095
            int arr = idx >> 10;             // 0=Ah 1=Al 2=Bh 3=Bl
            int rem = idx & 1023;
            int row = rem >> 3, q = rem & 7;
            const char* src = srcs[arr] + row * 128 + q * 16;
            uint32 dst = sb + (uint32)(arr * PLANE + row * ROWB + q * 16);
            CP_ASYNC16(dst, src);
        }
        asm volatile("cp.async.commit_group;" ::: "memory");
        asm volatile("cp.async.wait_group 0;" ::: "memory");
    }
    __syncthreads();

    float c[4][4][4];
    #pragma unroll
    for (int mt = 0; mt < 4; mt++)
        #pragma unroll
        for (int nt2 = 0; nt2 < 4; nt2++)
            #pragma unroll
            for (int e = 0; e < 4; e++) c[mt][nt2][e] = 0.0f;

    // ---- per-lane ldmatrix base addresses (bytes, shared space) ----
    const uint32 sbA = smem_u32(Ah);
    const uint32 sbB = smem_u32(Bh);
    uint32 aAddr[4], bAddr[2];
    {
        int rA = (lane & 7) + (lane & 8);
        int kA = (lane >> 4) * 4;
        #pragma unroll
        for (int mt = 0; mt < 4; mt++)
            aAddr[mt] = sbA + (uint32)(((wrow + mt * 16 + rA) * LDW + kA) * 4);
        int rB = (lane & 7) + ((lane & 16) >> 1);
        int kB = ((lane >> 3) & 1) * 4;
        #pragma unroll
        for (int p = 0; p < 2; p++)
            bAddr[p] = sbB + (uint32)(((wcol + p * 16 + rB) * LDW + kB) * 4);
    }

    // ---- mainloop: 4 k-steps of 16 ----
    #pragma unroll
    for (int ks = 0; ks < 4; ks++) {
        uint32 bh[2][4], bl[2][4];
        #pragma unroll
        for (int p = 0; p < 2; p++) {
            LDSM_X4(bh[p], bAddr[p]);
            LDSM_X4(bl[p], bAddr[p] + AL_OFF);
            bAddr[p] += 32;
        }
        #pragma unroll
        for (int mt = 0; mt < 4; mt++) {
            uint32 ah[4], al[4];
            LDSM_X4(ah, aAddr[mt]);
            LDSM_X4(al, aAddr[mt] + AL_OFF);
            aAddr[mt] += 32;
            #pragma unroll
            for (int nt2 = 0; nt2 < 4; nt2++) {
                int p = nt2 >> 1, o = (nt2 & 1) * 2;
                uint32 b0h = bh[p][o], b1h = bh[p][o + 1];
                uint32 b0l = bl[p][o], b1l = bl[p][o + 1];
                MMA_BF16(c[mt][nt2], ah, b0h, b1h);
                MMA_BF16(c[mt][nt2], ah, b0l, b1l);
                MMA_BF16(c[mt][nt2], al, b0h, b1h);
            }
        }
    }
    __syncthreads();

    // ---- epilogue ----
    float* stage = sm;   // 128 x SS floats = 67584 B < SIM_SMEM
    const bool diag = (bi == bj);

    #pragma unroll
    for (int mt = 0; mt < 4; mt++)
        #pragma unroll
        for (int nt2 = 0; nt2 < 4; nt2++) {
            int rs = wrow + mt * 16 + g;
            int cs = wcol + nt2 * 8 + 2 * t;
            float s0 = sigm(c[mt][nt2][0]);
            float s1 = sigm(c[mt][nt2][1]);
            float s2 = sigm(c[mt][nt2][2]);
            float s3 = sigm(c[mt][nt2][3]);

            int gj = j0 + cs;
            int gi = i0 + rs;
            if (gi < N) {
                if (gj + 1 < N)      *(float2*)(out + (size_t)gi * N + gj) = make_float2(s0, s1);
                else if (gj < N)     out[(size_t)gi * N + gj] = s0;
            }
            int gi2 = gi + 8;
            if (gi2 < N) {
                if (gj + 1 < N)      *(float2*)(out + (size_t)gi2 * N + gj) = make_float2(s2, s3);
                else if (gj < N)     out[(size_t)gi2 * N + gj] = s2;
            }

            if (!diag) {
                *(float2*)&stage[rs * SS + cs]       = make_float2(s0, s1);
                *(float2*)&stage[(rs + 8) * SS + cs] = make_float2(s2, s3);
            }
        }

    if (!diag) {
        __syncthreads();
        const int cbase = (wid & 3) * 32;
        const int rhalf = wid >> 2;
        int ci = cbase + lane;
        int gi_t = j0 + ci;
        bool rowok = (gi_t < N);
        #pragma unroll
        for (int itr = 0; itr < 8; itr++) {
            int rq = rhalf + itr * 2;
            int r8 = rq * 8;
            float v[8];
            #pragma unroll
            for (int e = 0; e < 8; e++)
                v[e] = stage[(r8 + e) * SS + ci];
            if (!rowok) continue;
            int gj = i0 + r8;
            float* orow = out + (size_t)gi_t * N + gj;
            if (gj + 7 < N) {
                *(float4*)orow       = make_float4(v[0], v[1], v[2], v[3]);
                *(float4*)(orow + 4) = make_float4(v[4], v[5], v[6], v[7]);
            } else {
                #pragma unroll
                for (int e = 0; e < 8; e++)
                    if (gj + e < N) orow[e] = v[e];
            }
        }
    }
}

// ---------------- launch --------------------------------------------------------
extern "C" void kernel_launch(void* const* d_in, const int* in_sizes, int n_in,
                              void* d_out, int out_size)
{
    const float* x    = (const float*)d_in[0];
    const void*  ei   = d_in[1];
    const float* W1   = (const float*)d_in[2];
    const float* b1   = (const float*)d_in[3];
    const float* W2   = (const float*)d_in[4];
    const float* atts = (const float*)d_in[5];
    const float* attd = (const float*)d_in[6];
    const float* gb   = (const float*)d_in[7];

    const int N = in_sizes[0] / IN_DIM;
    const int E = in_sizes[1] / 2;
    const int ET = E + N;

    float* out = (float*)d_out;
    float* out_embed =
        ((size_t)out_size >= (size_t)N * N + (size_t)N * HID)
            ? out + (size_t)N * N : nullptr;

    static int smem_set = 0;
    if (!smem_set) {
        cudaFuncSetAttribute(sim_mma, cudaFuncAttributeMaxDynamicSharedMemorySize,
                             SIM_SMEM);
        smem_set = 1;
    }

    node_fwd_init<<<(N + 31) / 32, 256>>>(x, W1, b1, W2, atts, attd, ei, N); // 1
    edge_max<<<(ET + 255) / 256, 256>>>(ei, E, N);                           // 2
    edge_scatter<<<(ET * 8 + 255) / 256, 256>>>(ei, E, N);                   // 3
    finalize_embed<<<(MAXN * HID + 255) / 256, 256>>>(gb, out_embed, N);     // 4

    const int nt = (N + 127) / 128;
    const int tri = nt * (nt + 1) / 2;
    sim_mma<<<tri, 256, SIM_SMEM>>>(out, N, nt);                             // 5
}